// round 1
// baseline (speedup 1.0000x reference)
#include <cuda_runtime.h>
#include <cuda_bf16.h>
#include <math.h>

// Problem constants (fixed by the reference)
#define B_   2
#define T_   8192
#define C_   1024
#define H_   64
#define M_   (B_ * T_)      // 16384 rows
#define HALF_WIN 16         // j in [t-16, t] -> 17 keys
#define WIN_KEYS 17

// Scratch for projections (allocation-free rule: device globals)
__device__ float g_q[(size_t)M_ * H_];
__device__ float g_k[(size_t)M_ * H_];
__device__ float g_v[(size_t)M_ * H_];

// ---------------------------------------------------------------------------
// Kernel A: projections. out = x @ W for W in {Wq, Wk, Wv} (blockIdx.y picks).
// Tile: 64 rows x 64 cols (full N), K-chunk 16. 256 threads, 4x4 reg tile.
// ---------------------------------------------------------------------------
__global__ __launch_bounds__(256) void proj_kernel(
    const float* __restrict__ x,
    const float* __restrict__ Wq,
    const float* __restrict__ Wk,
    const float* __restrict__ Wv)
{
    const float* W;
    float* out;
    if (blockIdx.y == 0)      { W = Wq; out = g_q; }
    else if (blockIdx.y == 1) { W = Wk; out = g_k; }
    else                      { W = Wv; out = g_v; }

    __shared__ float sx[64][17];   // +1 pad: kill bank conflicts on column reads
    __shared__ float sw[16][64];

    const int tid = threadIdx.x;        // 0..255
    const int tx  = tid & 15;           // col group
    const int ty  = tid >> 4;           // row group
    const int row0 = blockIdx.x * 64;

    float acc[4][4];
    #pragma unroll
    for (int i = 0; i < 4; i++)
        #pragma unroll
        for (int j = 0; j < 4; j++)
            acc[i][j] = 0.0f;

    for (int k0 = 0; k0 < C_; k0 += 16) {
        // Load x tile: 64x16 = 1024 elems, 4 per thread
        #pragma unroll
        for (int i = 0; i < 4; i++) {
            int e = tid + i * 256;
            int r = e >> 4, c = e & 15;
            sx[r][c] = x[(size_t)(row0 + r) * C_ + k0 + c];
        }
        // Load W tile: 16x64 = 1024 elems, fully coalesced
        #pragma unroll
        for (int i = 0; i < 4; i++) {
            int e = tid + i * 256;
            int r = e >> 6, c = e & 63;
            sw[r][c] = W[(size_t)(k0 + r) * H_ + c];
        }
        __syncthreads();

        #pragma unroll
        for (int kk = 0; kk < 16; kk++) {
            float a[4];
            #pragma unroll
            for (int i = 0; i < 4; i++) a[i] = sx[ty * 4 + i][kk];
            // vectorized b read (tx*4 is 16B aligned in sw row)
            float4 bv = *reinterpret_cast<const float4*>(&sw[kk][tx * 4]);
            float b[4] = {bv.x, bv.y, bv.z, bv.w};
            #pragma unroll
            for (int i = 0; i < 4; i++)
                #pragma unroll
                for (int j = 0; j < 4; j++)
                    acc[i][j] = fmaf(a[i], b[j], acc[i][j]);
        }
        __syncthreads();
    }

    #pragma unroll
    for (int i = 0; i < 4; i++) {
        float4 o = make_float4(acc[i][0], acc[i][1], acc[i][2], acc[i][3]);
        *reinterpret_cast<float4*>(&out[(size_t)(row0 + ty * 4 + i) * H_ + tx * 4]) = o;
    }
}

// ---------------------------------------------------------------------------
// Kernel B: windowed causal attention. One warp per (b,t).
// scores_j = q . k_j / 8 for j in [t-16, t]; softmax; out = sum p_j * v_j.
// ---------------------------------------------------------------------------
__global__ __launch_bounds__(256) void attn_kernel(float* __restrict__ out)
{
    const int warp = threadIdx.x >> 5;
    const int lane = threadIdx.x & 31;
    const int idx  = blockIdx.x * 8 + warp;     // global token index b*T + t
    if (idx >= M_) return;

    const int b = idx / T_;
    const int t = idx - b * T_;

    const float* qrow = g_q + (size_t)idx * H_;
    const float q0 = qrow[lane];
    const float q1 = qrow[lane + 32];

    const float* kbase = g_k + (size_t)b * T_ * H_;
    const float* vbase = g_v + (size_t)b * T_ * H_;

    float sc[WIN_KEYS];
    #pragma unroll
    for (int jj = 0; jj < WIN_KEYS; jj++) {
        const int j = t - HALF_WIN + jj;
        float s = -INFINITY;
        if (j >= 0) {
            const float* krow = kbase + (size_t)j * H_;
            float part = q0 * krow[lane] + q1 * krow[lane + 32];
            #pragma unroll
            for (int off = 16; off > 0; off >>= 1)
                part += __shfl_xor_sync(0xffffffffu, part, off);
            s = part * 0.125f;   // 1/sqrt(64)
        }
        sc[jj] = s;
    }

    // softmax over the 17 scores (all lanes hold identical values)
    float m = sc[0];
    #pragma unroll
    for (int jj = 1; jj < WIN_KEYS; jj++) m = fmaxf(m, sc[jj]);
    float sum = 0.0f;
    #pragma unroll
    for (int jj = 0; jj < WIN_KEYS; jj++) {
        sc[jj] = __expf(sc[jj] - m);   // exp(-inf) -> 0
        sum += sc[jj];
    }
    const float inv = 1.0f / sum;

    float o0 = 0.0f, o1 = 0.0f;
    #pragma unroll
    for (int jj = 0; jj < WIN_KEYS; jj++) {
        const int j = t - HALF_WIN + jj;
        if (j >= 0) {
            const float p = sc[jj] * inv;
            const float* vrow = vbase + (size_t)j * H_;
            o0 = fmaf(p, vrow[lane],      o0);
            o1 = fmaf(p, vrow[lane + 32], o1);
        }
    }

    out[(size_t)idx * H_ + lane]      = o0;
    out[(size_t)idx * H_ + lane + 32] = o1;
}

// ---------------------------------------------------------------------------
extern "C" void kernel_launch(void* const* d_in, const int* in_sizes, int n_in,
                              void* d_out, int out_size)
{
    const float* x  = (const float*)d_in[0];
    const float* Wq = (const float*)d_in[1];
    const float* Wk = (const float*)d_in[2];
    const float* Wv = (const float*)d_in[3];
    float* out = (float*)d_out;

    dim3 pgrid(M_ / 64, 3);
    proj_kernel<<<pgrid, 256>>>(x, Wq, Wk, Wv);

    attn_kernel<<<M_ / 8, 256>>>(out);
}

// round 2
// speedup vs baseline: 1.7193x; 1.7193x over previous
#include <cuda_runtime.h>
#include <cuda_fp16.h>
#include <math.h>

// Problem constants (fixed by the reference)
#define B_   2
#define T_   8192
#define C_   1024
#define H_   64
#define M_   (B_ * T_)      // 16384 rows
#define NTOT 192            // q|k|v concatenated
#define HALF_WIN 16
#define WIN_KEYS 17
#define KC   32             // K chunk per smem stage (two k16 blocks)

// Scratch (allocation-free rule: device globals)
__device__ float g_q[(size_t)M_ * H_];
__device__ float g_k[(size_t)M_ * H_];
__device__ float g_v[(size_t)M_ * H_];
// Split weights, n-major layout: [192][1024] halfs (row n = mat*64+col, k contiguous)
__device__ __half g_wh[(size_t)NTOT * C_];
__device__ __half g_wl[(size_t)NTOT * C_];

// ---------------------------------------------------------------------------
// Kernel 0: split W into fp16 hi/lo, transposed to n-major [n][k].
// ---------------------------------------------------------------------------
__global__ __launch_bounds__(256) void split_w_kernel(
    const float* __restrict__ Wq,
    const float* __restrict__ Wk,
    const float* __restrict__ Wv)
{
    int idx = blockIdx.x * 256 + threadIdx.x;       // [0, 192*1024)
    if (idx >= NTOT * C_) return;
    int nrow = idx >> 10;       // 0..191
    int k    = idx & 1023;
    int mat  = nrow >> 6;
    int n    = nrow & 63;
    const float* W = (mat == 0) ? Wq : (mat == 1) ? Wk : Wv;
    float f = W[(size_t)k * H_ + n];
    __half h = __float2half_rn(f);
    __half l = __float2half_rn(f - __half2float(h));
    g_wh[idx] = h;
    g_wl[idx] = l;
}

// Interleave within a k16 block so that one LDS.64 at halfs-offset 4t yields
// logical k {2t, 2t+1, 2t+8, 2t+9} (the m16n8k16 fragment order).
// For even r, pair (r, r+1) maps to contiguous physical (p, p+1).
__device__ __forceinline__ int kperm_even(int r) {       // r even, 0..15
    return ((r & 6) << 1) | ((r >> 3) << 1);
}

__device__ __forceinline__ void mma16816(float c[4],
    unsigned a0, unsigned a1, unsigned a2, unsigned a3,
    unsigned b0, unsigned b1)
{
    asm volatile(
        "mma.sync.aligned.m16n8k16.row.col.f32.f16.f16.f32 "
        "{%0,%1,%2,%3}, {%4,%5,%6,%7}, {%8,%9}, {%0,%1,%2,%3};\n"
        : "+f"(c[0]), "+f"(c[1]), "+f"(c[2]), "+f"(c[3])
        : "r"(a0), "r"(a1), "r"(a2), "r"(a3), "r"(b0), "r"(b1));
}

// ---------------------------------------------------------------------------
// Kernel A: fused projection GEMM via f16-split tensor-core MMA.
// CTA: 64 rows x 192 cols (q|k|v), K=1024 in chunks of 32.
// 8 warps: warp_m = wid&3 (m16 tile), warp_n = wid>>2 (96-wide n half).
// Each k16 block stored unpadded as [rows][16] halfs: 4 consecutive rows =
// 128 B = one LDS.64 phase -> conflict-free fragment loads.
// ---------------------------------------------------------------------------
__global__ __launch_bounds__(256) void proj_mma_kernel(const float* __restrict__ x)
{
    __shared__ __align__(16) __half sAh[2][64][16];
    __shared__ __align__(16) __half sAl[2][64][16];
    __shared__ __align__(16) __half sBh[2][NTOT][16];
    __shared__ __align__(16) __half sBl[2][NTOT][16];

    const int tid    = threadIdx.x;
    const int lane   = tid & 31;
    const int wid    = tid >> 5;
    const int g      = lane >> 2;     // 0..7
    const int t      = lane & 3;      // 0..3
    const int warp_m = wid & 3;
    const int warp_n = wid >> 2;
    const int row0   = blockIdx.x * 64;

    float acc[12][4];
    #pragma unroll
    for (int i = 0; i < 12; i++)
        #pragma unroll
        for (int j = 0; j < 4; j++) acc[i][j] = 0.0f;

    for (int k0 = 0; k0 < C_; k0 += KC) {
        // ---- stage x tile: 64 rows x 32 k, as fp16 hi/lo pairs (1024 pairs)
        #pragma unroll
        for (int i = 0; i < 4; i++) {
            int e   = tid + i * 256;
            int row = e >> 4;
            int c   = (e & 15) * 2;           // logical k within chunk, even
            int kb  = c >> 4;
            int r   = c & 15;
            int p   = kperm_even(r);
            float2 v = *reinterpret_cast<const float2*>(
                &x[(size_t)(row0 + row) * C_ + k0 + c]);
            __half hx = __float2half_rn(v.x);
            __half hy = __float2half_rn(v.y);
            __half lx = __float2half_rn(v.x - __half2float(hx));
            __half ly = __float2half_rn(v.y - __half2float(hy));
            *reinterpret_cast<__half2*>(&sAh[kb][row][p]) = __halves2half2(hx, hy);
            *reinterpret_cast<__half2*>(&sAl[kb][row][p]) = __halves2half2(lx, ly);
        }
        // ---- stage W tile: 192 n-rows x 32 k (3072 pairs), already split
        #pragma unroll
        for (int i = 0; i < 12; i++) {
            int e  = tid + i * 256;
            int n  = e >> 4;
            int c  = (e & 15) * 2;
            int kb = c >> 4;
            int r  = c & 15;
            int p  = kperm_even(r);
            __half2 h2 = *reinterpret_cast<const __half2*>(&g_wh[(size_t)n * C_ + k0 + c]);
            __half2 l2 = *reinterpret_cast<const __half2*>(&g_wl[(size_t)n * C_ + k0 + c]);
            *reinterpret_cast<__half2*>(&sBh[kb][n][p]) = h2;
            *reinterpret_cast<__half2*>(&sBl[kb][n][p]) = l2;
        }
        __syncthreads();

        #pragma unroll
        for (int kb = 0; kb < 2; kb++) {
            const int ra = warp_m * 16 + g;
            uint2 Ah_lo = *reinterpret_cast<const uint2*>(&sAh[kb][ra][4 * t]);
            uint2 Ah_hi = *reinterpret_cast<const uint2*>(&sAh[kb][ra + 8][4 * t]);
            uint2 Al_lo = *reinterpret_cast<const uint2*>(&sAl[kb][ra][4 * t]);
            uint2 Al_hi = *reinterpret_cast<const uint2*>(&sAl[kb][ra + 8][4 * t]);
            // a0 = row g k-lo, a1 = row g+8 k-lo, a2 = row g k-hi, a3 = row g+8 k-hi
            unsigned ah0 = Ah_lo.x, ah1 = Ah_hi.x, ah2 = Ah_lo.y, ah3 = Ah_hi.y;
            unsigned al0 = Al_lo.x, al1 = Al_hi.x, al2 = Al_lo.y, al3 = Al_hi.y;

            #pragma unroll
            for (int nt = 0; nt < 12; nt++) {
                const int n = warp_n * 96 + nt * 8 + g;
                uint2 Bh = *reinterpret_cast<const uint2*>(&sBh[kb][n][4 * t]);
                uint2 Bl = *reinterpret_cast<const uint2*>(&sBl[kb][n][4 * t]);
                mma16816(acc[nt], ah0, ah1, ah2, ah3, Bh.x, Bh.y); // hi*hi
                mma16816(acc[nt], ah0, ah1, ah2, ah3, Bl.x, Bl.y); // hi*lo
                mma16816(acc[nt], al0, al1, al2, al3, Bh.x, Bh.y); // lo*hi
            }
        }
        __syncthreads();
    }

    // ---- epilogue: write q/k/v
    const int rowA = row0 + warp_m * 16 + g;
    const int rowB = rowA + 8;
    #pragma unroll
    for (int nt = 0; nt < 12; nt++) {
        int nbase = warp_n * 96 + nt * 8;
        int mat   = nbase >> 6;
        int col   = (nbase & 63) + 2 * t;
        float* out = (mat == 0) ? g_q : (mat == 1) ? g_k : g_v;
        *reinterpret_cast<float2*>(&out[(size_t)rowA * H_ + col]) =
            make_float2(acc[nt][0], acc[nt][1]);
        *reinterpret_cast<float2*>(&out[(size_t)rowB * H_ + col]) =
            make_float2(acc[nt][2], acc[nt][3]);
    }
}

// ---------------------------------------------------------------------------
// Kernel B: windowed causal attention. One warp per (b,t). (unchanged)
// ---------------------------------------------------------------------------
__global__ __launch_bounds__(256) void attn_kernel(float* __restrict__ out)
{
    const int warp = threadIdx.x >> 5;
    const int lane = threadIdx.x & 31;
    const int idx  = blockIdx.x * 8 + warp;
    if (idx >= M_) return;

    const int b = idx / T_;
    const int t = idx - b * T_;

    const float* qrow = g_q + (size_t)idx * H_;
    const float q0 = qrow[lane];
    const float q1 = qrow[lane + 32];

    const float* kbase = g_k + (size_t)b * T_ * H_;
    const float* vbase = g_v + (size_t)b * T_ * H_;

    float sc[WIN_KEYS];
    #pragma unroll
    for (int jj = 0; jj < WIN_KEYS; jj++) {
        const int j = t - HALF_WIN + jj;
        float s = -INFINITY;
        if (j >= 0) {
            const float* krow = kbase + (size_t)j * H_;
            float part = q0 * krow[lane] + q1 * krow[lane + 32];
            #pragma unroll
            for (int off = 16; off > 0; off >>= 1)
                part += __shfl_xor_sync(0xffffffffu, part, off);
            s = part * 0.125f;
        }
        sc[jj] = s;
    }

    float m = sc[0];
    #pragma unroll
    for (int jj = 1; jj < WIN_KEYS; jj++) m = fmaxf(m, sc[jj]);
    float sum = 0.0f;
    #pragma unroll
    for (int jj = 0; jj < WIN_KEYS; jj++) {
        sc[jj] = __expf(sc[jj] - m);
        sum += sc[jj];
    }
    const float inv = 1.0f / sum;

    float o0 = 0.0f, o1 = 0.0f;
    #pragma unroll
    for (int jj = 0; jj < WIN_KEYS; jj++) {
        const int j = t - HALF_WIN + jj;
        if (j >= 0) {
            const float p = sc[jj] * inv;
            const float* vrow = vbase + (size_t)j * H_;
            o0 = fmaf(p, vrow[lane],      o0);
            o1 = fmaf(p, vrow[lane + 32], o1);
        }
    }

    out[(size_t)idx * H_ + lane]      = o0;
    out[(size_t)idx * H_ + lane + 32] = o1;
}

// ---------------------------------------------------------------------------
extern "C" void kernel_launch(void* const* d_in, const int* in_sizes, int n_in,
                              void* d_out, int out_size)
{
    const float* x  = (const float*)d_in[0];
    const float* Wq = (const float*)d_in[1];
    const float* Wk = (const float*)d_in[2];
    const float* Wv = (const float*)d_in[3];
    float* out = (float*)d_out;

    split_w_kernel<<<(NTOT * C_ + 255) / 256, 256>>>(Wq, Wk, Wv);
    proj_mma_kernel<<<M_ / 64, 256>>>(x);
    attn_kernel<<<M_ / 8, 256>>>(out);
}

// round 4
// speedup vs baseline: 2.4219x; 1.4086x over previous
#include <cuda_runtime.h>
#include <cuda_fp16.h>
#include <math.h>
#include <stdint.h>

// Problem constants (fixed by the reference)
#define B_   2
#define T_   8192
#define C_   1024
#define H_   64
#define M_   (B_ * T_)      // 16384 rows
#define NTOT 192            // q|k|v concatenated
#define HALF_WIN 16
#define WIN_KEYS 17
#define KC   32             // K chunk
#define NCH  (C_ / KC)      // 32 chunks

// Scratch (allocation-free rule: device globals)
__device__ float g_q[(size_t)M_ * H_];
__device__ float g_k[(size_t)M_ * H_];
__device__ float g_v[(size_t)M_ * H_];
// Weights pre-split (fp16 hi/lo) and pre-permuted into the smem image layout:
// [ch][hl][kb][n(192)][16 halfs]  -> one chunk stage = 24576 B, cp.async verbatim.
#define WST_CHUNK_BYTES (2 * 2 * NTOT * 32)     // 24576
__device__ __align__(16) uint4 g_wst[(size_t)NCH * WST_CHUNK_BYTES / 16];

// ---------------------------------------------------------------------------
// helpers
// ---------------------------------------------------------------------------
__device__ __forceinline__ uint32_t smem_u32(const void* p) {
    return (uint32_t)__cvta_generic_to_shared(p);
}

__device__ __forceinline__ void cp_async16(uint32_t dst, const void* src) {
    asm volatile("cp.async.cg.shared.global [%0], [%1], 16;"
                 :: "r"(dst), "l"(src) : "memory");
}
#define CP_COMMIT() asm volatile("cp.async.commit_group;" ::: "memory")
#define CP_WAIT0()  asm volatile("cp.async.wait_group 0;" ::: "memory")

__device__ __forceinline__ void mma16816(float c[4],
    unsigned a0, unsigned a1, unsigned a2, unsigned a3,
    unsigned b0, unsigned b1)
{
    asm volatile(
        "mma.sync.aligned.m16n8k16.row.col.f32.f16.f16.f32 "
        "{%0,%1,%2,%3}, {%4,%5,%6,%7}, {%8,%9}, {%0,%1,%2,%3};\n"
        : "+f"(c[0]), "+f"(c[1]), "+f"(c[2]), "+f"(c[3])
        : "r"(a0), "r"(a1), "r"(a2), "r"(a3), "r"(b0), "r"(b1));
}

// pack two floats -> half2 bits; residuals returned
__device__ __forceinline__ uint32_t pack2(float x, float y, float& rx, float& ry) {
    __half hx = __float2half_rn(x), hy = __float2half_rn(y);
    rx = x - __half2float(hx);
    ry = y - __half2float(hy);
    __half2 h = __halves2half2(hx, hy);
    return *reinterpret_cast<uint32_t*>(&h);
}

// ---------------------------------------------------------------------------
// Kernel 0: split + permute W into the cp.async-ready stage layout.
// One block per (chunk, mat): coalesced read of W[k0..k0+32)[0..64) into smem,
// then each thread emits one (hl,kb,n) row of 16 permuted halfs (2x uint4).
// Physical pair order within a k16 block: [p0,p4,p1,p5,p2,p6,p3,p7]
// (fragment uint2 at 8t holds logical k {2t,2t+1,2t+8,2t+9}).
// ---------------------------------------------------------------------------
__global__ __launch_bounds__(256) void split_w_kernel(
    const float* __restrict__ Wq,
    const float* __restrict__ Wk,
    const float* __restrict__ Wv)
{
    __shared__ float tw[32][64];
    const int ch  = blockIdx.x;     // 0..31
    const int mat = blockIdx.y;     // 0..2
    const int tid = threadIdx.x;
    const float* W = (mat == 0) ? Wq : (mat == 1) ? Wk : Wv;

    #pragma unroll
    for (int i = 0; i < 8; i++) {
        int idx = tid + i * 256;            // < 2048
        int kk  = idx >> 6, n = idx & 63;
        tw[kk][n] = W[(size_t)(ch * 32 + kk) * H_ + n];
    }
    __syncthreads();

    const int hl = tid >> 7;          // 0 hi, 1 lo
    const int kb = (tid >> 6) & 1;
    const int n  = tid & 63;

    uint32_t ph[8], pl[8];
    #pragma unroll
    for (int pr = 0; pr < 8; pr++) {
        float f0 = tw[kb * 16 + 2 * pr][n];
        float f1 = tw[kb * 16 + 2 * pr + 1][n];
        float r0, r1, d0, d1;
        ph[pr] = pack2(f0, f1, r0, r1);
        pl[pr] = pack2(r0, r1, d0, d1);
    }
    const uint32_t* p = hl ? pl : ph;
    uint4 w0 = make_uint4(p[0], p[4], p[1], p[5]);
    uint4 w1 = make_uint4(p[2], p[6], p[3], p[7]);

    size_t u4 = ((size_t)ch * WST_CHUNK_BYTES
               + (((hl * 2 + kb) * NTOT) + mat * 64 + n) * 32) / 16;
    g_wst[u4]     = w0;
    g_wst[u4 + 1] = w1;
}

// ---------------------------------------------------------------------------
// Kernel A: projection GEMM, fp16 hi/lo split (3 MMAs/k16), double-buffered.
// CTA = 128 rows x 192 cols. 8 warps: warp_m = wid&3 (32 rows = 2 m16),
// warp_n = wid>>2 (96 cols = 12 n8).
// Stage (40960 B):  A_hi [kb][128][16] @0 (8K) | A_lo @8192 (8K) |
//                   B    [hl][kb][192][16] @16384 (24K, cp.async verbatim)
// ---------------------------------------------------------------------------
#define STAGE_BYTES 40960
#define SMEM_PROJ   (2 * STAGE_BYTES)

__global__ void __launch_bounds__(256, 1) proj_kernel(const float* __restrict__ x)
{
    extern __shared__ __align__(16) char sm[];
    const uint32_t smb  = smem_u32(sm);
    const int tid   = threadIdx.x;
    const int lane  = tid & 31;
    const int g     = lane >> 2;       // 0..7
    const int t     = lane & 3;        // 0..3
    const int wid   = tid >> 5;
    const int warp_m = wid & 3;
    const int warp_n = wid >> 2;
    const int row0  = blockIdx.x * 128;

    // staging identity: one (row, kb) k16 block of A per thread
    const int a_row = tid >> 1;
    const int a_kb  = tid & 1;
    const float* a_src0 = x + (size_t)(row0 + a_row) * C_ + a_kb * 16;
    const uint32_t a_dst_off = a_kb * 4096 + a_row * 32;   // within A_hi region

    float acc[2][12][4];
    #pragma unroll
    for (int mi = 0; mi < 2; mi++)
        #pragma unroll
        for (int nt = 0; nt < 12; nt++)
            #pragma unroll
            for (int j = 0; j < 4; j++) acc[mi][nt][j] = 0.0f;

    for (int ch = -1; ch < NCH; ch++) {
        // ---------------- prefetch / stage chunk ch+1 ----------------
        float4 a4[4];
        const int chn = ch + 1;
        const uint32_t nxt = (chn & 1) * STAGE_BYTES;
        if (chn < NCH) {
            // B via cp.async (verbatim image)
            const char* src = reinterpret_cast<const char*>(g_wst)
                            + (size_t)chn * WST_CHUNK_BYTES;
            uint32_t dst = smb + nxt + 16384;
            #pragma unroll
            for (int i = 0; i < 6; i++) {
                int u = tid + i * 256;          // < 1536
                cp_async16(dst + u * 16, src + (size_t)u * 16);
            }
            CP_COMMIT();
            // A via LDG into regs
            const float* s = a_src0 + chn * KC;
            #pragma unroll
            for (int q = 0; q < 4; q++)
                a4[q] = *reinterpret_cast<const float4*>(s + q * 4);
        }

        // ---------------- compute on chunk ch ----------------
        if (ch >= 0) {
            const uint32_t cur = (ch & 1) * STAGE_BYTES;
            const uint32_t Ah = cur;
            const uint32_t Al = cur + 8192;
            const uint32_t Bh = cur + 16384;
            const uint32_t Bl = cur + 16384 + 12288;

            #pragma unroll
            for (int kb = 0; kb < 2; kb++) {
                unsigned ah[2][4], al[2][4];
                #pragma unroll
                for (int mi = 0; mi < 2; mi++) {
                    const int ra = warp_m * 32 + mi * 16 + g;
                    uint32_t offL = kb * 4096 + ra * 32 + 8 * t;
                    uint32_t offH = offL + 8 * 32;
                    uint2 AhL = *reinterpret_cast<const uint2*>(sm + Ah + offL);
                    uint2 AhH = *reinterpret_cast<const uint2*>(sm + Ah + offH);
                    uint2 AlL = *reinterpret_cast<const uint2*>(sm + Al + offL);
                    uint2 AlH = *reinterpret_cast<const uint2*>(sm + Al + offH);
                    ah[mi][0] = AhL.x; ah[mi][1] = AhH.x; ah[mi][2] = AhL.y; ah[mi][3] = AhH.y;
                    al[mi][0] = AlL.x; al[mi][1] = AlH.x; al[mi][2] = AlL.y; al[mi][3] = AlH.y;
                }
                #pragma unroll
                for (int nt = 0; nt < 12; nt++) {
                    const int n = warp_n * 96 + nt * 8 + g;
                    uint32_t boff = kb * 6144 + n * 32 + 8 * t;
                    uint2 bh = *reinterpret_cast<const uint2*>(sm + Bh + boff);
                    uint2 bl = *reinterpret_cast<const uint2*>(sm + Bl + boff);
                    #pragma unroll
                    for (int mi = 0; mi < 2; mi++) {
                        mma16816(acc[mi][nt], ah[mi][0], ah[mi][1], ah[mi][2], ah[mi][3], bh.x, bh.y);
                        mma16816(acc[mi][nt], ah[mi][0], ah[mi][1], ah[mi][2], ah[mi][3], bl.x, bl.y);
                        mma16816(acc[mi][nt], al[mi][0], al[mi][1], al[mi][2], al[mi][3], bh.x, bh.y);
                    }
                }
            }
        }

        // ---------------- finish staging chunk ch+1 ----------------
        if (chn < NCH) {
            uint32_t ph[8], pl[8];
            #pragma unroll
            for (int q = 0; q < 4; q++) {
                float r0, r1, r2, r3, d0, d1;
                ph[q * 2]     = pack2(a4[q].x, a4[q].y, r0, r1);
                ph[q * 2 + 1] = pack2(a4[q].z, a4[q].w, r2, r3);
                pl[q * 2]     = pack2(r0, r1, d0, d1);
                pl[q * 2 + 1] = pack2(r2, r3, d0, d1);
            }
            char* base = sm + nxt + a_dst_off;
            *reinterpret_cast<uint4*>(base)        = make_uint4(ph[0], ph[4], ph[1], ph[5]);
            *reinterpret_cast<uint4*>(base + 16)   = make_uint4(ph[2], ph[6], ph[3], ph[7]);
            *reinterpret_cast<uint4*>(base + 8192) = make_uint4(pl[0], pl[4], pl[1], pl[5]);
            *reinterpret_cast<uint4*>(base + 8208) = make_uint4(pl[2], pl[6], pl[3], pl[7]);
            CP_WAIT0();
        }
        __syncthreads();
    }

    // ---------------- epilogue ----------------
    #pragma unroll
    for (int mi = 0; mi < 2; mi++) {
        const int rowA = row0 + warp_m * 32 + mi * 16 + g;
        const int rowB = rowA + 8;
        #pragma unroll
        for (int nt = 0; nt < 12; nt++) {
            int nbase = warp_n * 96 + nt * 8;
            int mat   = nbase >> 6;
            int col   = (nbase & 63) + 2 * t;
            float* outp = (mat == 0) ? g_q : (mat == 1) ? g_k : g_v;
            *reinterpret_cast<float2*>(&outp[(size_t)rowA * H_ + col]) =
                make_float2(acc[mi][nt][0], acc[mi][nt][1]);
            *reinterpret_cast<float2*>(&outp[(size_t)rowB * H_ + col]) =
                make_float2(acc[mi][nt][2], acc[mi][nt][3]);
        }
    }
}

// ---------------------------------------------------------------------------
// Kernel B: windowed causal attention, smem-tiled.
// CTA = 128 tokens; stage k/v rows [tb-16, tb+128) into smem (144 rows each).
// Warp w handles tokens tb + w*16 .. +16 with the shfl-reduce scheme.
// ---------------------------------------------------------------------------
#define ATT_ROWS 144
#define SMEM_ATT (2 * ATT_ROWS * H_ * 4)    // 73728

__global__ void __launch_bounds__(256, 1) attn_kernel(float* __restrict__ out)
{
    extern __shared__ __align__(16) float skv[];
    float* sk = skv;
    float* sv = skv + ATT_ROWS * H_;

    const int tid  = threadIdx.x;
    const int lane = tid & 31;
    const int w    = tid >> 5;
    const int tb   = blockIdx.x * 128;          // global token base
    const int bstart = (tb / T_) * T_;

    // stage k/v (zero-fill rows before batch start)
    #pragma unroll
    for (int i = 0; i < 9; i++) {
        int idx = tid + i * 256;                // < 2304
        int row = idx >> 4, c4 = (idx & 15) * 4;
        int gr  = tb - HALF_WIN + row;
        float4 kv = make_float4(0.f, 0.f, 0.f, 0.f), vv = kv;
        if (gr >= bstart) {
            kv = *reinterpret_cast<const float4*>(&g_k[(size_t)gr * H_ + c4]);
            vv = *reinterpret_cast<const float4*>(&g_v[(size_t)gr * H_ + c4]);
        }
        *reinterpret_cast<float4*>(&sk[row * H_ + c4]) = kv;
        *reinterpret_cast<float4*>(&sv[row * H_ + c4]) = vv;
    }
    __syncthreads();

    const int t0 = tb + w * 16;
    float q0n = g_q[(size_t)t0 * H_ + lane];
    float q1n = g_q[(size_t)t0 * H_ + lane + 32];

    for (int it = 0; it < 16; it++) {
        const int tl = w * 16 + it;             // local token
        const int tg = tb + tl;                 // global token
        const float q0 = q0n, q1 = q1n;
        if (it + 1 < 16) {
            q0n = g_q[(size_t)(tg + 1) * H_ + lane];
            q1n = g_q[(size_t)(tg + 1) * H_ + lane + 32];
        }

        float sc[WIN_KEYS];
        #pragma unroll
        for (int jj = 0; jj < WIN_KEYS; jj++) {
            const int sr = tl + jj;             // smem row of key j = tg-16+jj
            float part = q0 * sk[sr * H_ + lane] + q1 * sk[sr * H_ + lane + 32];
            #pragma unroll
            for (int off = 16; off > 0; off >>= 1)
                part += __shfl_xor_sync(0xffffffffu, part, off);
            sc[jj] = (tg - HALF_WIN + jj >= bstart) ? part * 0.125f : -INFINITY;
        }

        float m = sc[0];
        #pragma unroll
        for (int jj = 1; jj < WIN_KEYS; jj++) m = fmaxf(m, sc[jj]);
        float sum = 0.0f;
        #pragma unroll
        for (int jj = 0; jj < WIN_KEYS; jj++) {
            sc[jj] = __expf(sc[jj] - m);        // exp(-inf) -> 0
            sum += sc[jj];
        }
        const float inv = 1.0f / sum;

        float o0 = 0.0f, o1 = 0.0f;
        #pragma unroll
        for (int jj = 0; jj < WIN_KEYS; jj++) {
            const float p = sc[jj] * inv;       // 0 for masked rows (zeros in smem)
            const int sr = tl + jj;
            o0 = fmaf(p, sv[sr * H_ + lane],      o0);
            o1 = fmaf(p, sv[sr * H_ + lane + 32], o1);
        }

        out[(size_t)tg * H_ + lane]      = o0;
        out[(size_t)tg * H_ + lane + 32] = o1;
    }
}

// ---------------------------------------------------------------------------
extern "C" void kernel_launch(void* const* d_in, const int* in_sizes, int n_in,
                              void* d_out, int out_size)
{
    const float* x  = (const float*)d_in[0];
    const float* Wq = (const float*)d_in[1];
    const float* Wk = (const float*)d_in[2];
    const float* Wv = (const float*)d_in[3];
    float* out = (float*)d_out;

    static bool attr_set = false;
    if (!attr_set) {
        cudaFuncSetAttribute(proj_kernel,
                             cudaFuncAttributeMaxDynamicSharedMemorySize, SMEM_PROJ);
        cudaFuncSetAttribute(attn_kernel,
                             cudaFuncAttributeMaxDynamicSharedMemorySize, SMEM_ATT);
        attr_set = true;
    }

    split_w_kernel<<<dim3(NCH, 3), 256>>>(Wq, Wk, Wv);
    proj_kernel<<<M_ / 128, 256, SMEM_PROJ>>>(x);
    attn_kernel<<<M_ / 128, 256, SMEM_ATT>>>(out);
}